// round 11
// baseline (speedup 1.0000x reference)
#include <cuda_runtime.h>
#include <cstdint>
#include <math.h>

#define BB 8
#define CC 256
#define HH 96
#define WW 128
#define HWSZ (HH*WW)
#define RD 4
#define ND 9
#define TILE_H 8
#define TILE_W 32
#define NTHREADS 288          // 4 g(8px) * 8 ty * 9 dy
#define CHUNK 8
#define NCHUNK 32
#define NBUF 4

#define FQ_PITCH 44
#define FR_PITCH 36
#define FQ_STG (CHUNK*16*FQ_PITCH)
#define FR_STG (CHUNK*8*FR_PITCH)
#define FQ_F (NBUF*FQ_STG)
#define FR_F (NBUF*FR_STG)
#define FRN_F 256
#define FQN_F 704
#define SMEM_FLOATS (FQ_F + FR_F + FRN_F + FQN_F)
#define SMEM_BYTES  (SMEM_FLOATS * 4)

#define FQ_SLOTS 1280
#define TOT_SLOTS 1792
#define NSLOT_IT 7

typedef unsigned long long u64;

__device__ __forceinline__ void cpasync16(unsigned sa, const float* src) {
    asm volatile("cp.async.cg.shared.global [%0], [%1], 16;\n" :: "r"(sa), "l"(src));
}
__device__ __forceinline__ unsigned smem_u32(const void* p) {
    return (unsigned)__cvta_generic_to_shared(p);
}
__device__ __forceinline__ u64 pack2(float lo, float hi) {
    u64 r; asm("mov.b64 %0, {%1, %2};" : "=l"(r) : "f"(lo), "f"(hi)); return r;
}
__device__ __forceinline__ void unpack2(float& lo, float& hi, u64 v) {
    asm("mov.b64 {%0, %1}, %2;" : "=f"(lo), "=f"(hi) : "l"(v));
}
__device__ __forceinline__ void fma2(u64& d, u64 a, u64 b) {
    asm("fma.rn.f32x2 %0, %1, %2, %0;" : "+l"(d) : "l"(a), "l"(b));
}

#define STAGE(BUFL) do {                                                    \
    _Pragma("unroll")                                                       \
    for (int it = 0; it < NSLOT_IT; ++it) {                                 \
        if (val[it]) cpasync16(dst[it] + (BUFL) * dlt[it], src[it]);        \
        src[it] += (size_t)CHUNK * HWSZ;                                    \
    }                                                                       \
    asm volatile("cp.async.commit_group;\n");                               \
} while (0)

#define COMP(BUFL) do {                                                     \
    const float* sfqb_ = sm + (BUFL) * FQ_STG;                              \
    const float* sfrb_ = sm + FQ_F + (BUFL) * FR_STG;                       \
    _Pragma("unroll")                                                       \
    for (int ch = 0; ch < CHUNK; ++ch) {                                    \
        const float* fqc = sfqb_ + ch * (16*FQ_PITCH);                      \
        const float* frc = sfrb_ + ch * (8*FR_PITCH);                       \
        float4 fA = *(const float4*)(frc + foff);                           \
        float4 fB = *(const float4*)(frc + foff + 4);                       \
        const float* rp = fqc + qoff;                                       \
        float4 q0 = *(const float4*)(rp);                                   \
        float4 q1 = *(const float4*)(rp + 4);                               \
        float4 q2 = *(const float4*)(rp + 8);                               \
        float4 q3 = *(const float4*)(rp + 12);                              \
        float qv0 = fqc[o0], qv1 = fqc[o1];                                 \
        fqs0 = fmaf(qv0, qv0, fqs0);                                        \
        fqs1 = fmaf(qv1, qv1, fqs1);                                        \
        if (tid < 64) { float qv2 = fqc[o2];                                \
                        fqs2 = fmaf(qv2, qv2, fqs2); }                      \
        float fv[8] = {fA.x, fA.y, fA.z, fA.w, fB.x, fB.y, fB.z, fB.w};     \
        if (dy == RD) {                                                     \
            _Pragma("unroll")                                               \
            for (int i = 0; i < 8; ++i) frs[i] = fmaf(fv[i], fv[i], frs[i]);\
        }                                                                   \
        float q[16] = {q0.x,q0.y,q0.z,q0.w, q1.x,q1.y,q1.z,q1.w,            \
                       q2.x,q2.y,q2.z,q2.w, q3.x,q3.y,q3.z,q3.w};           \
        u64 fp[4], qp[15];                                                  \
        _Pragma("unroll")                                                   \
        for (int i2 = 0; i2 < 4; ++i2)                                      \
            fp[i2] = pack2(fv[2*i2], fv[2*i2+1]);                           \
        _Pragma("unroll")                                                   \
        for (int j = 0; j < 15; ++j)                                        \
            qp[j] = pack2(q[j], q[j+1]);                                    \
        _Pragma("unroll")                                                   \
        for (int i2 = 0; i2 < 4; ++i2)                                      \
            _Pragma("unroll")                                               \
            for (int dx = 0; dx < ND; ++dx)                                 \
                fma2(acc2[i2*ND + dx], fp[i2], qp[2*i2 + dx]);              \
    }                                                                       \
} while (0)

#define ITER(K, SB, CB) do {                                                \
    if ((K) + 2 < NCHUNK) { STAGE(SB); }                                    \
    else { asm volatile("cp.async.commit_group;\n"); }                      \
    asm volatile("cp.async.wait_group 2;\n");                               \
    __syncthreads();                                                        \
    COMP(CB);                                                               \
} while (0)

__global__ __launch_bounds__(NTHREADS, 1)
void corr_kernel(const float* __restrict__ fr, const float* __restrict__ fq,
                 float* __restrict__ out) {
    extern __shared__ float sm[];
    float* s_fq  = sm;
    float* s_fr  = sm + FQ_F;
    float* s_frn = sm + FQ_F + FR_F;
    float* s_fqn = s_frn + FRN_F;

    const int b  = blockIdx.z;
    const int h0 = blockIdx.y * TILE_H;
    const int w0 = blockIdx.x * TILE_W;
    const int tid = threadIdx.x;
    const int g  = tid & 3;
    const int ty = (tid >> 2) & 7;
    const int dy = tid >> 5;          // warp-uniform

    const float* frb = fr + (size_t)b * CC * HWSZ;
    const float* fqb = fq + (size_t)b * CC * HWSZ;

    const int foff = ty * FR_PITCH + 8 * g;
    const int qoff = (ty + dy) * FQ_PITCH + 8 * g;

    const int o0 = (tid / 40) * FQ_PITCH + (tid % 40);
    const int p1 = tid + NTHREADS;
    const int o1 = (p1 / 40) * FQ_PITCH + (p1 % 40);
    const int p2 = tid + 2 * NTHREADS;
    const int o2 = (p2 / 40) * FQ_PITCH + (p2 % 40);

    // ---- precompute staging slots ----
    const float* src[NSLOT_IT];
    unsigned dst[NSLOT_IT], dlt[NSLOT_IT];
    bool val[NSLOT_IT];
    #pragma unroll
    for (int it = 0; it < NSLOT_IT; ++it) {
        int idx = tid + it * NTHREADS;
        val[it] = false; src[it] = frb; dst[it] = smem_u32(sm); dlt[it] = 0;
        if (idx < FQ_SLOTS) {
            int ch  = idx / 160;
            int rem = idx - ch * 160;
            int row = rem / 10;
            int c16 = rem - row * 10;
            int hg = h0 + row - RD;
            int wg = w0 + c16 * 4 - RD;
            bool v = (hg >= 0 && hg < HH && wg >= 0 && wg <= WW - 4);
            val[it] = v;
            dst[it] = smem_u32(s_fq + (ch * 16 + row) * FQ_PITCH + c16 * 4);
            dlt[it] = FQ_STG * 4;
            if (v) src[it] = fqb + (size_t)ch * HWSZ + hg * WW + wg;
        } else if (idx < TOT_SLOTS) {
            int j   = idx - FQ_SLOTS;
            int ch  = j >> 6;
            int rem = j & 63;
            int row = rem >> 3;
            int c16 = rem & 7;
            val[it] = true;
            dst[it] = smem_u32(s_fr + (ch * 8 + row) * FR_PITCH + c16 * 4);
            dlt[it] = FR_STG * 4;
            src[it] = frb + (size_t)ch * HWSZ + (h0 + row) * WW + (w0 + c16 * 4);
        }
    }

    // zero fq buffers once (OOB halo + pad cols never overwritten by cp.async)
    for (int i = tid; i < FQ_F; i += NTHREADS) s_fq[i] = 0.f;
    __syncthreads();

    u64 acc2[36];
    #pragma unroll
    for (int i = 0; i < 36; ++i) acc2[i] = 0ull;
    float frs[8] = {0,0,0,0,0,0,0,0};
    float fqs0 = 0.f, fqs1 = 0.f, fqs2 = 0.f;

    STAGE(0);
    STAGE(1);

    #pragma unroll 1
    for (int kb = 0; kb < NCHUNK / 4; ++kb) {
        const int k0 = kb * 4;
        ITER(k0 + 0, 2, 0);
        ITER(k0 + 1, 3, 1);
        ITER(k0 + 2, 0, 2);
        ITER(k0 + 3, 1, 3);
    }

    // ---- exchange inverse norms through smem ----
    if (dy == RD) {
        #pragma unroll
        for (int i = 0; i < 8; ++i)
            s_frn[ty * TILE_W + 8 * g + i] = 1.0f / fmaxf(sqrtf(frs[i]), 1e-12f);
    }
    s_fqn[o0] = 1.0f / fmaxf(sqrtf(fqs0), 1e-12f);
    s_fqn[o1] = 1.0f / fmaxf(sqrtf(fqs1), 1e-12f);
    if (tid < 64)
        s_fqn[o2] = 1.0f / fmaxf(sqrtf(fqs2), 1e-12f);
    __syncthreads();

    const int h = h0 + ty;
    const int w_base = w0 + 8 * g;

    float invfr[8];
    #pragma unroll
    for (int i = 0; i < 8; ++i)
        invfr[i] = s_frn[ty * TILE_W + 8 * g + i];

    float invq[16];
    #pragma unroll
    for (int j = 0; j < 16; ++j)
        invq[j] = s_fqn[(ty + dy) * FQ_PITCH + 8 * g + j];

    // unpack accumulators
    float acc[72];
    #pragma unroll
    for (int i2 = 0; i2 < 4; ++i2)
        #pragma unroll
        for (int dx = 0; dx < ND; ++dx) {
            float lo, hi;
            unpack2(lo, hi, acc2[i2*ND + dx]);
            acc[(2*i2)*ND + dx]   = lo;
            acc[(2*i2+1)*ND + dx] = hi;
        }

    const float scale = 1.0f / (float)CC;
    #pragma unroll
    for (int dx = 0; dx < ND; ++dx) {
        float4 oA, oB;
        oA.x = acc[0*ND + dx] * invfr[0] * invq[0 + dx] * scale;
        oA.y = acc[1*ND + dx] * invfr[1] * invq[1 + dx] * scale;
        oA.z = acc[2*ND + dx] * invfr[2] * invq[2 + dx] * scale;
        oA.w = acc[3*ND + dx] * invfr[3] * invq[3 + dx] * scale;
        oB.x = acc[4*ND + dx] * invfr[4] * invq[4 + dx] * scale;
        oB.y = acc[5*ND + dx] * invfr[5] * invq[5 + dx] * scale;
        oB.z = acc[6*ND + dx] * invfr[6] * invq[6 + dx] * scale;
        oB.w = acc[7*ND + dx] * invfr[7] * invq[7 + dx] * scale;
        size_t off = (((size_t)b * (ND*ND) + (size_t)(dy*ND + dx)) * HH + h) * WW + w_base;
        *(float4*)&out[off]     = oA;
        *(float4*)&out[off + 4] = oB;
    }
}

extern "C" void kernel_launch(void* const* d_in, const int* in_sizes, int n_in,
                              void* d_out, int out_size) {
    const float* fr = (const float*)d_in[0];
    const float* fq = (const float*)d_in[1];
    float* out = (float*)d_out;
    (void)in_sizes; (void)n_in; (void)out_size;

    cudaFuncSetAttribute(corr_kernel, cudaFuncAttributeMaxDynamicSharedMemorySize, SMEM_BYTES);

    dim3 grid(WW / TILE_W, HH / TILE_H, BB);   // (4, 12, 8) = 384 CTAs
    corr_kernel<<<grid, NTHREADS, SMEM_BYTES>>>(fr, fq, out);
}

// round 12
// speedup vs baseline: 1.0793x; 1.0793x over previous
#include <cuda_runtime.h>
#include <cstdint>
#include <math.h>

#define BB 8
#define CC 256
#define HH 96
#define WW 128
#define HWSZ (HH*WW)
#define RD 4
#define ND 9

#define HQB 8            // hq rows per CTA (one per warp)
#define WT 16            // w tile
#define NB 24            // B columns (WT + 2*RD)
#define KC 16            // channels per stage
#define NSTG (CC/KC)     // 16
#define APITCH 20        // k-row pitch (16 used + 4 pad) -> ldmatrix conflict-free
#define BPITCH 20
#define NTHREADS 256

// smem float offsets
#define SA_STG (16*16*APITCH)          // 5120 per buffer (16 h x 16 px)
#define SB_OFF (2*SA_STG)              // 10240
#define SB_STG (HQB*NB*BPITCH)         // 3840
#define SINVA_OFF (SB_OFF + 2*SB_STG)  // 17920
#define SINVB_OFF (SINVA_OFF + 256)
#define SMEM_FLOATS (SINVB_OFF + HQB*NB)
#define SMEM_BYTES (SMEM_FLOATS*4)

typedef unsigned int u32;

__device__ __forceinline__ unsigned smem_u32(const void* p) {
    return (unsigned)__cvta_generic_to_shared(p);
}
__device__ __forceinline__ u32 cvt_tf32(float v) {
    u32 r; asm("cvt.rna.tf32.f32 %0, %1;" : "=r"(r) : "f"(v)); return r;
}
__device__ __forceinline__ void mma_tf32(float c[4], const u32 a[4], const u32 b[2]) {
    asm volatile(
        "mma.sync.aligned.m16n8k8.row.col.f32.tf32.tf32.f32 "
        "{%0,%1,%2,%3}, {%4,%5,%6,%7}, {%8,%9}, {%0,%1,%2,%3};"
        : "+f"(c[0]), "+f"(c[1]), "+f"(c[2]), "+f"(c[3])
        : "r"(a[0]), "r"(a[1]), "r"(a[2]), "r"(a[3]), "r"(b[0]), "r"(b[1]));
}
__device__ __forceinline__ void ldm_x4(u32 r[4], unsigned addr) {
    asm volatile("ldmatrix.sync.aligned.m8n8.x4.shared.b16 {%0,%1,%2,%3}, [%4];"
                 : "=r"(r[0]), "=r"(r[1]), "=r"(r[2]), "=r"(r[3]) : "r"(addr));
}
__device__ __forceinline__ void ldm_x2(u32 r[2], unsigned addr) {
    asm volatile("ldmatrix.sync.aligned.m8n8.x2.shared.b16 {%0,%1}, [%2];"
                 : "=r"(r[0]), "=r"(r[1]) : "r"(addr));
}

__global__ __launch_bounds__(NTHREADS, 1)
void corr_mma_kernel(const float* __restrict__ fr, const float* __restrict__ fq,
                     float* __restrict__ out) {
    extern __shared__ float sm[];
    const int tid  = threadIdx.x;
    const int wid  = tid >> 5;
    const int lane = tid & 31;

    const int b   = blockIdx.z;
    const int hq0 = blockIdx.y * HQB;
    const int w0  = blockIdx.x * WT;

    // ---- A staging role: thread owns (alh, apx): all channels of fr[ah][w0+apx]
    const int apx = tid & 15;
    const int alh = tid >> 4;            // 0..15
    const int ah  = hq0 - 4 + alh;
    const bool av = (ah >= 0 && ah < HH);
    const float* aptr = fr + (size_t)b * CC * HWSZ + (av ? ah : 0) * WW + (w0 + apx);

    // ---- B staging role: threads 0..191 own (bhq, bpx)
    const int bpx = (tid < 192) ? (tid % NB) : 0;
    const int bhq = (tid < 192) ? (tid / NB) : 0;
    const int wq  = w0 - RD + bpx;
    const bool bv = (tid < 192) && (wq >= 0 && wq < WW);
    const float* bptr = fq + (size_t)b * CC * HWSZ + (hq0 + bhq) * WW + (bv ? wq : 0);

    float anrm = 0.f, bnrm = 0.f;
    float cAcc[27][4];
    #pragma unroll
    for (int i = 0; i < 27; ++i)
        #pragma unroll
        for (int j = 0; j < 4; ++j) cAcc[i][j] = 0.f;

    u32 ar[KC], br[KC];

    // LDG stage S into registers (with fused norm accumulation, fp32)
    #define LDGSTAGE(S) do {                                                 \
        const size_t coff = (size_t)(S) * KC * HWSZ;                         \
        _Pragma("unroll")                                                    \
        for (int kc = 0; kc < KC; ++kc) {                                    \
            float v = 0.f;                                                   \
            if (av) v = aptr[coff + (size_t)kc * HWSZ];                      \
            anrm = fmaf(v, v, anrm);                                         \
            ar[kc] = cvt_tf32(v);                                            \
        }                                                                    \
        _Pragma("unroll")                                                    \
        for (int kc = 0; kc < KC; ++kc) {                                    \
            float v = 0.f;                                                   \
            if (bv) v = bptr[coff + (size_t)kc * HWSZ];                      \
            bnrm = fmaf(v, v, bnrm);                                         \
            br[kc] = cvt_tf32(v);                                            \
        }                                                                    \
    } while (0)

    #define STSSTAGE(BUF) do {                                               \
        uint4* pa = (uint4*)(sm + (BUF) * SA_STG + (alh * 16 + apx) * APITCH);\
        pa[0] = make_uint4(ar[0], ar[1], ar[2], ar[3]);                      \
        pa[1] = make_uint4(ar[4], ar[5], ar[6], ar[7]);                      \
        pa[2] = make_uint4(ar[8], ar[9], ar[10], ar[11]);                    \
        pa[3] = make_uint4(ar[12], ar[13], ar[14], ar[15]);                  \
        if (tid < 192) {                                                     \
            uint4* pb = (uint4*)(sm + SB_OFF + (BUF) * SB_STG                \
                                 + (bhq * NB + bpx) * BPITCH);               \
            pb[0] = make_uint4(br[0], br[1], br[2], br[3]);                  \
            pb[1] = make_uint4(br[4], br[5], br[6], br[7]);                  \
            pb[2] = make_uint4(br[8], br[9], br[10], br[11]);                \
            pb[3] = make_uint4(br[12], br[13], br[14], br[15]);              \
        }                                                                    \
    } while (0)

    // one k-step (8 channels): load B frags, then per dy-tile ldmatrix A + 3 mma
    #define KSTEP(BUF, KS) do {                                              \
        u32 bF[3][2];                                                        \
        _Pragma("unroll")                                                    \
        for (int nt = 0; nt < 3; ++nt) {                                     \
            unsigned bd = smem_u32(sm + SB_OFF + (BUF) * SB_STG              \
                + (wid * NB + nt * 8 + (lane & 7)) * BPITCH                  \
                + (KS) * 8 + (((lane >> 3) & 1) << 2));                      \
            ldm_x2(bF[nt], bd);                                              \
        }                                                                    \
        _Pragma("unroll")                                                    \
        for (int dyt = 0; dyt < 9; ++dyt) {                                  \
            const int lh = wid + 8 - dyt;                                    \
            u32 aF[4];                                                       \
            unsigned ad = smem_u32(sm + (BUF) * SA_STG                       \
                + (lh * 16 + (lane & 15)) * APITCH                           \
                + (KS) * 8 + ((lane >> 4) << 2));                            \
            ldm_x4(aF, ad);                                                  \
            mma_tf32(cAcc[dyt * 3 + 0], aF, bF[0]);                          \
            mma_tf32(cAcc[dyt * 3 + 1], aF, bF[1]);                          \
            mma_tf32(cAcc[dyt * 3 + 2], aF, bF[2]);                          \
        }                                                                    \
    } while (0)

    // ---- pipeline: stage 0, then loop
    LDGSTAGE(0);
    STSSTAGE(0);
    __syncthreads();

    #pragma unroll 1
    for (int s = 0; s < NSTG; ++s) {
        const int buf = s & 1;
        if (s + 1 < NSTG) LDGSTAGE(s + 1);
        KSTEP(buf, 0);
        KSTEP(buf, 1);
        if (s + 1 < NSTG) {
            STSSTAGE(buf ^ 1);
        }
        __syncthreads();
    }

    // ---- norms to smem
    sm[SINVA_OFF + alh * 16 + apx] = 1.0f / fmaxf(sqrtf(anrm), 1e-12f);
    if (tid < 192)
        sm[SINVB_OFF + bhq * NB + bpx] = 1.0f / fmaxf(sqrtf(bnrm), 1e-12f);
    __syncthreads();

    // ---- epilogue
    const float scale = 1.0f / (float)CC;
    const int r1 = lane >> 2;            // C row (px) 0..7 ; +8 for c2/c3
    const int colb = 2 * (lane & 3);

    #pragma unroll
    for (int dyt = 0; dyt < 9; ++dyt) {
        const int h = hq0 + wid + 4 - dyt;
        if (h < 0 || h >= HH) continue;
        const int lh = wid + 8 - dyt;
        const float ia1 = sm[SINVA_OFF + lh * 16 + r1] * scale;
        const float ia2 = sm[SINVA_OFF + lh * 16 + r1 + 8] * scale;
        #pragma unroll
        for (int nt = 0; nt < 3; ++nt) {
            const int col0 = nt * 8 + colb;
            const float ib0 = sm[SINVB_OFF + wid * NB + col0];
            const float ib1 = sm[SINVB_OFF + wid * NB + col0 + 1];
            const float* cf = cAcc[dyt * 3 + nt];
            int dx;
            size_t pbase = ((size_t)b * 81 + dyt * ND) * HWSZ + h * WW + w0;
            dx = col0 - r1;
            if (dx >= 0 && dx < ND) out[pbase + (size_t)dx * HWSZ + r1] = cf[0] * ia1 * ib0;
            dx = col0 + 1 - r1;
            if (dx >= 0 && dx < ND) out[pbase + (size_t)dx * HWSZ + r1] = cf[1] * ia1 * ib1;
            dx = col0 - (r1 + 8);
            if (dx >= 0 && dx < ND) out[pbase + (size_t)dx * HWSZ + r1 + 8] = cf[2] * ia2 * ib0;
            dx = col0 + 1 - (r1 + 8);
            if (dx >= 0 && dx < ND) out[pbase + (size_t)dx * HWSZ + r1 + 8] = cf[3] * ia2 * ib1;
        }
    }
    #undef LDGSTAGE
    #undef STSSTAGE
    #undef KSTEP
}

extern "C" void kernel_launch(void* const* d_in, const int* in_sizes, int n_in,
                              void* d_out, int out_size) {
    const float* fr = (const float*)d_in[0];
    const float* fq = (const float*)d_in[1];
    float* out = (float*)d_out;
    (void)in_sizes; (void)n_in;

    // outputs whose fq row is fully out-of-range are exact zeros; main kernel
    // skips them, so zero-fill first (async memset is graph-capturable).
    cudaMemsetAsync(d_out, 0, (size_t)out_size * sizeof(float));

    cudaFuncSetAttribute(corr_mma_kernel,
                         cudaFuncAttributeMaxDynamicSharedMemorySize, SMEM_BYTES);

    dim3 grid(WW / WT, HH / HQB, BB);   // (8, 12, 8) = 768 CTAs
    corr_mma_kernel<<<grid, NTHREADS, SMEM_BYTES>>>(fr, fq, out);
}